// round 8
// baseline (speedup 1.0000x reference)
#include <cuda_runtime.h>
#include <math.h>
#include <limits.h>

#define LROW 2048
#define SDIM 65
#define OUT_PER_ROW (SDIM * SDIM)   // 4225
#define THRESH 0.2f
#define EPSV 1e-6f
#define NTHREADS 512

__global__ __launch_bounds__(NTHREADS, 4)
void rp_kernel(const float* __restrict__ x, float* __restrict__ out) {
    const int row = blockIdx.x;
    const int t = threadIdx.x;
    const float4* __restrict__ xr =
        reinterpret_cast<const float4*>(x + (size_t)row * LROW);

    // ---- one-pass row stats: 1 float4 per thread (512*4 = 2048) ----
    const float4 v0 = __ldcs(&xr[t]);            // idx 4t..4t+3 (t<17 holds first 68)

    float sum, sumsq;
    int mn = INT_MAX, mx = -1;
    {
        const float4 v = v0; const int base = t * 4;
        sum   = (v.x + v.y) + (v.z + v.w);
        sumsq = (v.x * v.x + v.y * v.y) + (v.z * v.z + v.w * v.w);
        if (v.x != 0.f) { mn = min(mn, base + 0); mx = max(mx, base + 0); }
        if (v.y != 0.f) { mn = min(mn, base + 1); mx = max(mx, base + 1); }
        if (v.z != 0.f) { mn = min(mn, base + 2); mx = max(mx, base + 2); }
        if (v.w != 0.f) { mn = min(mn, base + 3); mx = max(mx, base + 3); }
    }

    // ---- warp reduce ----
    #pragma unroll
    for (int o = 16; o > 0; o >>= 1) {
        sum   += __shfl_down_sync(0xffffffffu, sum, o);
        sumsq += __shfl_down_sync(0xffffffffu, sumsq, o);
        mn = min(mn, __shfl_down_sync(0xffffffffu, mn, o));
        mx = max(mx, __shfl_down_sync(0xffffffffu, mx, o));
    }

    __shared__ float s_sum[16], s_sq[16];
    __shared__ int   s_mn[16],  s_mx[16];
    const int wid = t >> 5, lid = t & 31;
    if (lid == 0) { s_sum[wid] = sum; s_sq[wid] = sumsq; s_mn[wid] = mn; s_mx[wid] = mx; }
    __syncthreads();

    __shared__ float s_mean, s_rstd;
    __shared__ int   s_start, s_end;
    if (t < 32) {
        sum   = (t < 16) ? s_sum[t] : 0.f;
        sumsq = (t < 16) ? s_sq[t]  : 0.f;
        mn    = (t < 16) ? s_mn[t]  : INT_MAX;
        mx    = (t < 16) ? s_mx[t]  : -1;
        #pragma unroll
        for (int o = 8; o > 0; o >>= 1) {
            sum   += __shfl_down_sync(0xffffffffu, sum, o);
            sumsq += __shfl_down_sync(0xffffffffu, sumsq, o);
            mn = min(mn, __shfl_down_sync(0xffffffffu, mn, o));
            mx = max(mx, __shfl_down_sync(0xffffffffu, mx, o));
        }
        if (t == 0) {
            const float cnt  = (mx >= 0) ? (float)(mx - mn + 1) : 1.f;
            const float mean = sum / cnt;
            const float var  = fmaxf(sumsq / cnt - mean * mean, 0.f);
            const float stdv = fmaxf(sqrtf(var), EPSV);
            s_mean = mean;
            s_rstd = 1.f / stdv;
            s_start = mn;
            s_end   = mx;
        }
    }
    __syncthreads();

    // ---- normalized first 65 values from registers (NaN = invalid mask) ----
    __shared__ float ys[SDIM];
    if (t < 17) {
        const float vals[4] = {v0.x, v0.y, v0.z, v0.w};
        const float mean = s_mean, rstd = s_rstd;
        const int st = s_start, en = s_end;
        #pragma unroll
        for (int e = 0; e < 4; e++) {
            const int idx = 4 * t + e;
            if (idx < SDIM) {
                const bool valid = (idx >= st) && (idx <= en);
                ys[idx] = valid ? (vals[e] - mean) * rstd
                                : __int_as_float(0x7fffffff);
            }
        }
    }
    __syncthreads();

    // ---- 65x65 matrix: warp-per-output-row, comparands in registers ----
    // 16 warps sweep 65 rows. Lane l holds ya=ys[l], yb=ys[l+32], yc=ys[64]:
    // zero conflicted LDS in the loop; stores are warp-coalesced STG.32.
    float* __restrict__ orow = out + (size_t)row * OUT_PER_ROW;
    const float ya = ys[lid];            // conflict-free
    const float yb = ys[lid + 32];       // conflict-free
    const float yc = ys[SDIM - 1];       // broadcast

    #pragma unroll 3
    for (int i = wid; i < SDIM; i += 16) {
        const float yi = ys[i];          // uniform per warp -> broadcast
        float* __restrict__ oi = orow + i * SDIM;
        __stcs(&oi[lid],      (fabsf(yi - ya) < THRESH) ? 1.f : 0.f);
        __stcs(&oi[lid + 32], (fabsf(yi - yb) < THRESH) ? 1.f : 0.f);
        if (lid == 0)
            __stcs(&oi[64],   (fabsf(yi - yc) < THRESH) ? 1.f : 0.f);
    }
}

extern "C" void kernel_launch(void* const* d_in, const int* in_sizes, int n_in,
                              void* d_out, int out_size) {
    const float* x = (const float*)d_in[0];
    float* out = (float*)d_out;
    const int nrows = in_sizes[0] / LROW;   // 1024*16 = 16384
    rp_kernel<<<nrows, NTHREADS>>>(x, out);
}

// round 9
// speedup vs baseline: 1.6807x; 1.6807x over previous
#include <cuda_runtime.h>
#include <math.h>
#include <limits.h>

#define LROW 2048
#define SDIM 65
#define OUT_PER_ROW (SDIM * SDIM)   // 4225
#define THRESH 0.2f
#define EPSV 1e-6f
#define NTHREADS 256

__global__ __launch_bounds__(NTHREADS, 8)
void rp_kernel(const float* __restrict__ x, float* __restrict__ out) {
    const int row = blockIdx.x;
    const int t = threadIdx.x;
    const float4* __restrict__ xr =
        reinterpret_cast<const float4*>(x + (size_t)row * LROW);

    // ---- one-pass row stats: sum, sumsq, min/max nonzero index ----
    // 2 independent LDG.128 per thread (MLP=2) — this shape is load-bearing.
    const float4 v0 = __ldcs(&xr[t]);            // idx 4t..4t+3 (t<17 holds first 68)
    const float4 v1 = __ldcs(&xr[t + NTHREADS]);

    float sum = 0.f, sumsq = 0.f;
    int mn = INT_MAX, mx = -1;
    {
        const float4 v = v0; const int base = t * 4;
        sum   += (v.x + v.y) + (v.z + v.w);
        sumsq += (v.x * v.x + v.y * v.y) + (v.z * v.z + v.w * v.w);
        if (v.x != 0.f) { mn = min(mn, base + 0); mx = max(mx, base + 0); }
        if (v.y != 0.f) { mn = min(mn, base + 1); mx = max(mx, base + 1); }
        if (v.z != 0.f) { mn = min(mn, base + 2); mx = max(mx, base + 2); }
        if (v.w != 0.f) { mn = min(mn, base + 3); mx = max(mx, base + 3); }
    }
    {
        const float4 v = v1; const int base = (t + NTHREADS) * 4;
        sum   += (v.x + v.y) + (v.z + v.w);
        sumsq += (v.x * v.x + v.y * v.y) + (v.z * v.z + v.w * v.w);
        if (v.x != 0.f) { mn = min(mn, base + 0); mx = max(mx, base + 0); }
        if (v.y != 0.f) { mn = min(mn, base + 1); mx = max(mx, base + 1); }
        if (v.z != 0.f) { mn = min(mn, base + 2); mx = max(mx, base + 2); }
        if (v.w != 0.f) { mn = min(mn, base + 3); mx = max(mx, base + 3); }
    }

    // ---- warp reduce ----
    #pragma unroll
    for (int o = 16; o > 0; o >>= 1) {
        sum   += __shfl_down_sync(0xffffffffu, sum, o);
        sumsq += __shfl_down_sync(0xffffffffu, sumsq, o);
        mn = min(mn, __shfl_down_sync(0xffffffffu, mn, o));
        mx = max(mx, __shfl_down_sync(0xffffffffu, mx, o));
    }

    __shared__ float s_sum[8], s_sq[8];
    __shared__ int   s_mn[8],  s_mx[8];
    const int wid = t >> 5, lid = t & 31;
    if (lid == 0) { s_sum[wid] = sum; s_sq[wid] = sumsq; s_mn[wid] = mn; s_mx[wid] = mx; }
    __syncthreads();

    __shared__ float s_mean, s_rstd;
    __shared__ int   s_start, s_end;
    if (t < 32) {
        sum   = (t < 8) ? s_sum[t] : 0.f;
        sumsq = (t < 8) ? s_sq[t]  : 0.f;
        mn    = (t < 8) ? s_mn[t]  : INT_MAX;
        mx    = (t < 8) ? s_mx[t]  : -1;
        #pragma unroll
        for (int o = 4; o > 0; o >>= 1) {
            sum   += __shfl_down_sync(0xffffffffu, sum, o);
            sumsq += __shfl_down_sync(0xffffffffu, sumsq, o);
            mn = min(mn, __shfl_down_sync(0xffffffffu, mn, o));
            mx = max(mx, __shfl_down_sync(0xffffffffu, mx, o));
        }
        if (t == 0) {
            const float cnt  = (mx >= 0) ? (float)(mx - mn + 1) : 1.f;
            const float mean = sum / cnt;
            const float var  = fmaxf(sumsq / cnt - mean * mean, 0.f);
            const float stdv = fmaxf(sqrtf(var), EPSV);
            s_mean = mean;
            s_rstd = 1.f / stdv;
            s_start = mn;
            s_end   = mx;
        }
    }
    __syncthreads();

    // ---- normalized first 65 values from registers (NaN = invalid mask) ----
    __shared__ float ys[SDIM];
    if (t < 17) {
        const float vals[4] = {v0.x, v0.y, v0.z, v0.w};
        const float mean = s_mean, rstd = s_rstd;
        const int st = s_start, en = s_end;
        #pragma unroll
        for (int e = 0; e < 4; e++) {
            const int idx = 4 * t + e;
            if (idx < SDIM) {
                const bool valid = (idx >= st) && (idx <= en);
                ys[idx] = valid ? (vals[e] - mean) * rstd
                                : __int_as_float(0x7fffffff);
            }
        }
    }
    __syncthreads();

    // ---- 65x65 matrix: warp-per-output-row, comparands in registers ----
    // Lane l holds ya=ys[l], yb=ys[l+32], yc=ys[64]: zero conflicted LDS.
    // Fully unrolled: 9 compile-time iterations (last one predicated).
    float* __restrict__ orow = out + (size_t)row * OUT_PER_ROW;
    const float ya = ys[lid];            // conflict-free
    const float yb = ys[lid + 32];       // conflict-free
    const float yc = ys[SDIM - 1];       // broadcast

    #pragma unroll
    for (int it = 0; it < 9; it++) {
        const int i = wid + it * 8;
        if (i < SDIM) {
            const float yi = ys[i];      // uniform per warp -> broadcast
            float* __restrict__ oi = orow + i * SDIM;
            __stcs(&oi[lid],      (fabsf(yi - ya) < THRESH) ? 1.f : 0.f);
            __stcs(&oi[lid + 32], (fabsf(yi - yb) < THRESH) ? 1.f : 0.f);
            if (lid == 0)
                __stcs(&oi[64],   (fabsf(yi - yc) < THRESH) ? 1.f : 0.f);
        }
    }
}

extern "C" void kernel_launch(void* const* d_in, const int* in_sizes, int n_in,
                              void* d_out, int out_size) {
    const float* x = (const float*)d_in[0];
    float* out = (float*)d_out;
    const int nrows = in_sizes[0] / LROW;   // 1024*16 = 16384
    rp_kernel<<<nrows, NTHREADS>>>(x, out);
}

// round 10
// speedup vs baseline: 1.7054x; 1.0147x over previous
#include <cuda_runtime.h>
#include <math.h>
#include <limits.h>

#define LROW 2048
#define SDIM 65
#define OUT_PER_ROW (SDIM * SDIM)   // 4225
#define THRESH 0.2f
#define EPSV 1e-6f
#define NTHREADS 128

__global__ __launch_bounds__(NTHREADS, 16)
void rp_kernel(const float* __restrict__ x, float* __restrict__ out) {
    const int row = blockIdx.x;
    const int t = threadIdx.x;
    const float4* __restrict__ xr =
        reinterpret_cast<const float4*>(x + (size_t)row * LROW);

    // ---- one-pass row stats: 4 independent LDG.128 per thread (MLP=4) ----
    const float4 v0 = __ldcs(&xr[t]);                 // t<17 holds first 68 vals
    const float4 v1 = __ldcs(&xr[t + NTHREADS]);
    const float4 v2 = __ldcs(&xr[t + 2 * NTHREADS]);
    const float4 v3 = __ldcs(&xr[t + 3 * NTHREADS]);

    float sum = 0.f, sumsq = 0.f;
    int mn = INT_MAX, mx = -1;
    #pragma unroll
    for (int p = 0; p < 4; p++) {
        const float4 v = (p == 0) ? v0 : (p == 1) ? v1 : (p == 2) ? v2 : v3;
        const int base = (t + p * NTHREADS) * 4;
        sum   += (v.x + v.y) + (v.z + v.w);
        sumsq += (v.x * v.x + v.y * v.y) + (v.z * v.z + v.w * v.w);
        if (v.x != 0.f) { mn = min(mn, base + 0); mx = max(mx, base + 0); }
        if (v.y != 0.f) { mn = min(mn, base + 1); mx = max(mx, base + 1); }
        if (v.z != 0.f) { mn = min(mn, base + 2); mx = max(mx, base + 2); }
        if (v.w != 0.f) { mn = min(mn, base + 3); mx = max(mx, base + 3); }
    }

    // ---- warp reduce ----
    #pragma unroll
    for (int o = 16; o > 0; o >>= 1) {
        sum   += __shfl_down_sync(0xffffffffu, sum, o);
        sumsq += __shfl_down_sync(0xffffffffu, sumsq, o);
        mn = min(mn, __shfl_down_sync(0xffffffffu, mn, o));
        mx = max(mx, __shfl_down_sync(0xffffffffu, mx, o));
    }

    __shared__ float s_sum[4], s_sq[4];
    __shared__ int   s_mn[4],  s_mx[4];
    const int wid = t >> 5, lid = t & 31;
    if (lid == 0) { s_sum[wid] = sum; s_sq[wid] = sumsq; s_mn[wid] = mn; s_mx[wid] = mx; }
    __syncthreads();

    __shared__ float s_mean, s_rstd;
    __shared__ int   s_start, s_end;
    if (t < 32) {
        sum   = (t < 4) ? s_sum[t] : 0.f;
        sumsq = (t < 4) ? s_sq[t]  : 0.f;
        mn    = (t < 4) ? s_mn[t]  : INT_MAX;
        mx    = (t < 4) ? s_mx[t]  : -1;
        #pragma unroll
        for (int o = 2; o > 0; o >>= 1) {
            sum   += __shfl_down_sync(0xffffffffu, sum, o);
            sumsq += __shfl_down_sync(0xffffffffu, sumsq, o);
            mn = min(mn, __shfl_down_sync(0xffffffffu, mn, o));
            mx = max(mx, __shfl_down_sync(0xffffffffu, mx, o));
        }
        if (t == 0) {
            const float cnt  = (mx >= 0) ? (float)(mx - mn + 1) : 1.f;
            const float mean = sum / cnt;
            const float var  = fmaxf(sumsq / cnt - mean * mean, 0.f);
            const float stdv = fmaxf(sqrtf(var), EPSV);
            s_mean = mean;
            s_rstd = 1.f / stdv;
            s_start = mn;
            s_end   = mx;
        }
    }
    __syncthreads();

    // ---- normalized first 65 values from registers (NaN = invalid mask) ----
    __shared__ float ys[SDIM];
    if (t < 17) {
        const float vals[4] = {v0.x, v0.y, v0.z, v0.w};
        const float mean = s_mean, rstd = s_rstd;
        const int st = s_start, en = s_end;
        #pragma unroll
        for (int e = 0; e < 4; e++) {
            const int idx = 4 * t + e;
            if (idx < SDIM) {
                const bool valid = (idx >= st) && (idx <= en);
                ys[idx] = valid ? (vals[e] - mean) * rstd
                                : __int_as_float(0x7fffffff);
            }
        }
    }
    __syncthreads();

    // ---- 65x65 matrix: warp-per-output-row, comparands in registers ----
    // 4 warps sweep 65 rows (17 iterations). Lane l holds ya/yb/yc in regs:
    // zero conflicted LDS in loop; stores are warp-coalesced STG.32.
    float* __restrict__ orow = out + (size_t)row * OUT_PER_ROW;
    const float ya = ys[lid];            // conflict-free
    const float yb = ys[lid + 32];       // conflict-free
    const float yc = ys[SDIM - 1];       // broadcast

    #pragma unroll 4
    for (int i = wid; i < SDIM; i += 4) {
        const float yi = ys[i];          // uniform per warp -> broadcast
        float* __restrict__ oi = orow + i * SDIM;
        __stcs(&oi[lid],      (fabsf(yi - ya) < THRESH) ? 1.f : 0.f);
        __stcs(&oi[lid + 32], (fabsf(yi - yb) < THRESH) ? 1.f : 0.f);
        if (lid == 0)
            __stcs(&oi[64],   (fabsf(yi - yc) < THRESH) ? 1.f : 0.f);
    }
}

extern "C" void kernel_launch(void* const* d_in, const int* in_sizes, int n_in,
                              void* d_out, int out_size) {
    const float* x = (const float*)d_in[0];
    float* out = (float*)d_out;
    const int nrows = in_sizes[0] / LROW;   // 1024*16 = 16384
    rp_kernel<<<nrows, NTHREADS>>>(x, out);
}